// round 13
// baseline (speedup 1.0000x reference)
#include <cuda_runtime.h>
#include <cstddef>
#include <cstdint>

constexpr int Bsz = 4, S = 4096, D = 256, C = 8921;
constexpr int CT = (C + 127) / 128;  // 70

// Raw fp32 smem tiles. A-type: [128 rows][32 k + 4 pad]. GEMM2 B: [32 k][128 n + 4 pad].
constexpr int TA   = 128 * 36;          // 4608 floats
constexpr int TB2  = 32 * 132;          // 4224 floats
constexpr int STG1 = 2 * TA;            // A + B (GEMM1), floats
constexpr int STG2 = TA + TB2;          // A + B (GEMM2), floats
constexpr int NSTG = 4;
constexpr int SM1  = NSTG * STG1 * 4;   // 147456 B
constexpr int SM2  = NSTG * STG2 * 4;   // 141312 B

__device__ __forceinline__ uint32_t t32(float v) {
    uint32_t u;
    asm("cvt.rna.tf32.f32 %0, %1;" : "=r"(u) : "f"(v));
    return u;
}
// split raw fp32 into tf32 hi + tf32 lo (both rounded)
__device__ __forceinline__ void split1(float v, uint32_t& h, uint32_t& l) {
    h = t32(v);
    l = t32(v - __uint_as_float(h));
}

__device__ __forceinline__ void mma8(float* c, const uint32_t* a, const uint32_t* b) {
    asm volatile(
        "mma.sync.aligned.m16n8k8.row.col.f32.tf32.tf32.f32 "
        "{%0,%1,%2,%3}, {%4,%5,%6,%7}, {%8,%9}, {%0,%1,%2,%3};"
        : "+f"(c[0]), "+f"(c[1]), "+f"(c[2]), "+f"(c[3])
        : "r"(a[0]), "r"(a[1]), "r"(a[2]), "r"(a[3]), "r"(b[0]), "r"(b[1]));
}

__device__ __forceinline__ uint32_t sptr(const void* p) {
    return (uint32_t)__cvta_generic_to_shared(p);
}
// 16B cp.async; srcsize=0 -> zero-fill (for C-edge rows)
__device__ __forceinline__ void cpa16(uint32_t dst, const float* src, uint32_t srcsize) {
    asm volatile("cp.async.cg.shared.global [%0], [%1], 16, %2;"
                 :: "r"(dst), "l"(src), "r"(srcsize) : "memory");
}
#define CP_COMMIT() asm volatile("cp.async.commit_group;" ::: "memory")
#define CP_WAIT2()  asm volatile("cp.async.wait_group 2;" ::: "memory")

// ---------------------------------------------------------------------------
// GEMM1: scores[b][c][s] = sum_d W[c][d] * x[b][s][d]   (tf32x3, cp.async x4)
// ---------------------------------------------------------------------------
__global__ __launch_bounds__(256)
void k_scores(const float* __restrict__ x, const float* __restrict__ W,
              float* __restrict__ att)
{
    extern __shared__ float sm[];
    const int tid = threadIdx.x, lane = tid & 31, warp = tid >> 5;
    const int wm = warp & 1, wn = warp >> 1;      // 2 x 4 warp grid
    const int g = lane >> 2, q = lane & 3;
    const int b = blockIdx.z, cBase = blockIdx.y * 128, sBase = blockIdx.x * 128;
    const float* xb = x + (size_t)b * S * D;

    const int lrow = tid >> 1, lcol = (tid & 1) * 16;
    const int arow = cBase + lrow;
    const uint32_t aSz = (arow < C) ? 16u : 0u;
    const float* aSrc = W + (size_t)(arow < C ? arow : 0) * D + lcol;
    const float* bSrc = xb + (size_t)(sBase + lrow) * D + lcol;
    const uint32_t sOff = (uint32_t)(lrow * 36 + lcol) * 4;
    const uint32_t smb = sptr(sm);

    // prologue: stages 0..2
#pragma unroll
    for (int st = 0; st < NSTG - 1; ++st) {
        uint32_t dA = smb + (uint32_t)st * STG1 * 4 + sOff;
        uint32_t dB = dA + TA * 4;
        const int kk = st * 32;
#pragma unroll
        for (int j = 0; j < 4; j++) {
            cpa16(dA + j * 16, aSrc + kk + j * 4, aSz);
            cpa16(dB + j * 16, bSrc + kk + j * 4, 16u);
        }
        CP_COMMIT();
    }

    float acc[4][4][4];
#pragma unroll
    for (int i = 0; i < 4; i++)
#pragma unroll
        for (int j = 0; j < 4; j++)
#pragma unroll
            for (int k = 0; k < 4; k++) acc[i][j][k] = 0.0f;

#pragma unroll 1
    for (int it = 0; it < 8; ++it) {
        CP_WAIT2();
        __syncthreads();
        {   // issue stage it+3 (empty commit past the end keeps group count fixed)
            const int st = it + NSTG - 1;
            if (st < 8) {
                uint32_t dA = smb + (uint32_t)(st & 3) * STG1 * 4 + sOff;
                uint32_t dB = dA + TA * 4;
                const int kk = st * 32;
#pragma unroll
                for (int j = 0; j < 4; j++) {
                    cpa16(dA + j * 16, aSrc + kk + j * 4, aSz);
                    cpa16(dB + j * 16, bSrc + kk + j * 4, 16u);
                }
            }
            CP_COMMIT();
        }
        const float* Ar = sm + (it & 3) * STG1;
        const float* Br = Ar + TA;

#pragma unroll
        for (int ks = 0; ks < 4; ks++) {
            const int kk = ks * 8;
            uint32_t ah[4][4], al[4][4];
#pragma unroll
            for (int mi = 0; mi < 4; mi++) {
                int i0 = (wm * 64 + mi * 16 + g) * 36 + kk + q;
                split1(Ar[i0],       ah[mi][0], al[mi][0]);
                split1(Ar[i0 + 288], ah[mi][1], al[mi][1]);
                split1(Ar[i0 + 4],   ah[mi][2], al[mi][2]);
                split1(Ar[i0 + 292], ah[mi][3], al[mi][3]);
            }
            uint32_t bh[4][2], bl[4][2];
#pragma unroll
            for (int ni = 0; ni < 4; ni++) {
                int i0 = (wn * 32 + ni * 8 + g) * 36 + kk + q;
                split1(Br[i0],     bh[ni][0], bl[ni][0]);
                split1(Br[i0 + 4], bh[ni][1], bl[ni][1]);
            }
#pragma unroll
            for (int mi = 0; mi < 4; mi++)
#pragma unroll
                for (int ni = 0; ni < 4; ni++) {
                    mma8(acc[mi][ni], ah[mi], bh[ni]);
                    mma8(acc[mi][ni], ah[mi], bl[ni]);
                    mma8(acc[mi][ni], al[mi], bh[ni]);
                }
        }
    }

    float* out = att + (size_t)b * C * S;
#pragma unroll
    for (int mi = 0; mi < 4; mi++) {
        int r = cBase + wm * 64 + mi * 16 + g;
#pragma unroll
        for (int ni = 0; ni < 4; ni++) {
            int cc = sBase + wn * 32 + ni * 8 + 2 * q;
            if (r < C)
                *(float2*)&out[(size_t)r * S + cc] = make_float2(acc[mi][ni][0], acc[mi][ni][1]);
            if (r + 8 < C)
                *(float2*)&out[(size_t)(r + 8) * S + cc] = make_float2(acc[mi][ni][2], acc[mi][ni][3]);
        }
    }
}

// ---------------------------------------------------------------------------
// Softmax over S, in place (proven; at its BW floor)
// ---------------------------------------------------------------------------
__global__ __launch_bounds__(256)
void k_softmax(float* __restrict__ att)
{
    float* p = att + (size_t)blockIdx.x * S;
    const int tid = threadIdx.x;
    float4 v[4];
    float mx = -3.4e38f;
#pragma unroll
    for (int l = 0; l < 4; l++) {
        v[l] = *(const float4*)&p[(size_t)(tid + l * 256) * 4];
        mx = fmaxf(mx, fmaxf(fmaxf(v[l].x, v[l].y), fmaxf(v[l].z, v[l].w)));
    }
    __shared__ float red[8];
#pragma unroll
    for (int o = 16; o; o >>= 1) mx = fmaxf(mx, __shfl_xor_sync(0xffffffffu, mx, o));
    if ((tid & 31) == 0) red[tid >> 5] = mx;
    __syncthreads();
    float m = red[0];
#pragma unroll
    for (int w = 1; w < 8; w++) m = fmaxf(m, red[w]);
    __syncthreads();
    float sum = 0.f;
#pragma unroll
    for (int l = 0; l < 4; l++) {
        v[l].x = __expf(v[l].x - m); v[l].y = __expf(v[l].y - m);
        v[l].z = __expf(v[l].z - m); v[l].w = __expf(v[l].w - m);
        sum += (v[l].x + v[l].y) + (v[l].z + v[l].w);
    }
#pragma unroll
    for (int o = 16; o; o >>= 1) sum += __shfl_xor_sync(0xffffffffu, sum, o);
    if ((tid & 31) == 0) red[tid >> 5] = sum;
    __syncthreads();
    float tot = 0.f;
#pragma unroll
    for (int w = 0; w < 8; w++) tot += red[w];
    const float inv = 1.0f / tot;
#pragma unroll
    for (int l = 0; l < 4; l++) {
        v[l].x *= inv; v[l].y *= inv; v[l].z *= inv; v[l].w *= inv;
        *(float4*)&p[(size_t)(tid + l * 256) * 4] = v[l];
    }
}

// ---------------------------------------------------------------------------
// GEMM2: logits[b][c][d] = sum_s att[b][c][s] * x[b][s][d]  (tf32x3, cp.async x4)
// ---------------------------------------------------------------------------
__global__ __launch_bounds__(256)
void k_av(const float* __restrict__ x, const float* __restrict__ att,
          float* __restrict__ logits)
{
    extern __shared__ float sm[];
    const int tid = threadIdx.x, lane = tid & 31, warp = tid >> 5;
    const int wm = warp & 1, wn = warp >> 1;
    const int g = lane >> 2, q = lane & 3;
    const int b = blockIdx.z, cBase = blockIdx.y * 128, dBase = blockIdx.x * 128;

    const float* xb = x + (size_t)b * S * D;
    const float* ab = att + (size_t)b * C * S;

    const int lrow = tid >> 1, lcol = (tid & 1) * 16;
    const int arow = cBase + lrow;
    const uint32_t aSz = (arow < C) ? 16u : 0u;
    const float* aSrc = ab + (size_t)(arow < C ? arow : 0) * S + lcol;
    const uint32_t aOff = (uint32_t)(lrow * 36 + lcol) * 4;

    const int brow = tid >> 3, bcol = (tid & 7) * 16;   // 32 rows x 128 cols
    const float* bSrc = xb + (size_t)brow * D + dBase + bcol;
    const uint32_t bOff = (uint32_t)TA * 4 + (uint32_t)(brow * 132 + bcol) * 4;
    const uint32_t smb = sptr(sm);

#pragma unroll
    for (int st = 0; st < NSTG - 1; ++st) {
        uint32_t base = smb + (uint32_t)st * STG2 * 4;
        const int kk = st * 32;
#pragma unroll
        for (int j = 0; j < 4; j++) {
            cpa16(base + aOff + j * 16, aSrc + kk + j * 4, aSz);
            cpa16(base + bOff + j * 16, bSrc + (size_t)kk * D + j * 4, 16u);
        }
        CP_COMMIT();
    }

    float acc[4][4][4];
#pragma unroll
    for (int i = 0; i < 4; i++)
#pragma unroll
        for (int j = 0; j < 4; j++)
#pragma unroll
            for (int k = 0; k < 4; k++) acc[i][j][k] = 0.0f;

#pragma unroll 1
    for (int it = 0; it < 128; ++it) {
        CP_WAIT2();
        __syncthreads();
        {
            const int st = it + NSTG - 1;
            if (st < 128) {
                uint32_t base = smb + (uint32_t)(st & 3) * STG2 * 4;
                const int kk = st * 32;
#pragma unroll
                for (int j = 0; j < 4; j++) {
                    cpa16(base + aOff + j * 16, aSrc + kk + j * 4, aSz);
                    cpa16(base + bOff + j * 16, bSrc + (size_t)kk * D + j * 4, 16u);
                }
            }
            CP_COMMIT();
        }
        const float* Ar = sm + (it & 3) * STG2;
        const float* Br = Ar + TA;

#pragma unroll
        for (int ks = 0; ks < 4; ks++) {
            const int kk = ks * 8;
            uint32_t ah[4][4], al[4][4];
#pragma unroll
            for (int mi = 0; mi < 4; mi++) {
                int i0 = (wm * 64 + mi * 16 + g) * 36 + kk + q;
                split1(Ar[i0],       ah[mi][0], al[mi][0]);
                split1(Ar[i0 + 288], ah[mi][1], al[mi][1]);
                split1(Ar[i0 + 4],   ah[mi][2], al[mi][2]);
                split1(Ar[i0 + 292], ah[mi][3], al[mi][3]);
            }
            uint32_t bh[4][2], bl[4][2];
#pragma unroll
            for (int ni = 0; ni < 4; ni++) {
                int i0 = (kk + q) * 132 + wn * 32 + ni * 8 + g;
                split1(Br[i0],       bh[ni][0], bl[ni][0]);
                split1(Br[i0 + 528], bh[ni][1], bl[ni][1]);   // +4 k rows
            }
#pragma unroll
            for (int mi = 0; mi < 4; mi++)
#pragma unroll
                for (int ni = 0; ni < 4; ni++) {
                    mma8(acc[mi][ni], ah[mi], bh[ni]);
                    mma8(acc[mi][ni], ah[mi], bl[ni]);
                    mma8(acc[mi][ni], al[mi], bh[ni]);
                }
        }
    }

    float* out = logits + (size_t)b * C * D;
#pragma unroll
    for (int mi = 0; mi < 4; mi++) {
        int r = cBase + wm * 64 + mi * 16 + g;
#pragma unroll
        for (int ni = 0; ni < 4; ni++) {
            int cc = dBase + wn * 32 + ni * 8 + 2 * q;
            if (r < C)
                *(float2*)&out[(size_t)r * D + cc] = make_float2(acc[mi][ni][0], acc[mi][ni][1]);
            if (r + 8 < C)
                *(float2*)&out[(size_t)(r + 8) * D + cc] = make_float2(acc[mi][ni][2], acc[mi][ni][3]);
        }
    }
}

// ---------------------------------------------------------------------------
extern "C" void kernel_launch(void* const* d_in, const int* in_sizes, int n_in,
                              void* d_out, int out_size)
{
    const float* x = (const float*)d_in[0];  // [B, S, D]
    const float* W = (const float*)d_in[1];  // [C, D]
    float* logits = (float*)d_out;                        // [B, C, D]
    float* att    = (float*)d_out + (size_t)Bsz * C * D;  // [B, C, S]

    cudaFuncSetAttribute(k_scores, cudaFuncAttributeMaxDynamicSharedMemorySize, SM1);
    cudaFuncSetAttribute(k_av, cudaFuncAttributeMaxDynamicSharedMemorySize, SM2);

    k_scores<<<dim3(S / 128, CT, Bsz), 256, SM1>>>(x, W, att);
    k_softmax<<<Bsz * C, 256>>>(att);
    k_av<<<dim3(D / 128, CT, Bsz), 256, SM2>>>(x, att, logits);
}

// round 16
// speedup vs baseline: 1.1544x; 1.1544x over previous
#include <cuda_runtime.h>
#include <cstddef>
#include <cstdint>

constexpr int Bsz = 4, S = 4096, D = 256, C = 8921;
constexpr int CT = (C + 127) / 128;  // 70

// Raw fp32 smem tiles. A-type: [128 rows][32 k + 4 pad]. GEMM2 B: [32 k][128 n + 4 pad].
constexpr int TA   = 128 * 36;          // 4608 floats
constexpr int TB2  = 32 * 132;          // 4224 floats
constexpr int STG1 = 2 * TA;            // A + B (GEMM1), floats
constexpr int STG2 = TA + TB2;          // A + B (GEMM2), floats
constexpr int NSTG = 3;
constexpr int SM1  = NSTG * STG1 * 4;   // 110592 B  -> 2 CTAs/SM
constexpr int SM2  = NSTG * STG2 * 4;   // 105984 B  -> 2 CTAs/SM

__device__ __forceinline__ uint32_t t32(float v) {
    uint32_t u;
    asm("cvt.rna.tf32.f32 %0, %1;" : "=r"(u) : "f"(v));
    return u;
}
// split raw fp32 into tf32 hi + residual lo (lo passed as raw fp32 bits;
// HMMA reads the tf32 field -> effective truncation of the tiny term, err ~2e-7)
__device__ __forceinline__ void split1(float v, uint32_t& h, uint32_t& l) {
    h = t32(v);
    l = __float_as_uint(v - __uint_as_float(h));
}

__device__ __forceinline__ void mma8(float* c, const uint32_t* a, const uint32_t* b) {
    asm volatile(
        "mma.sync.aligned.m16n8k8.row.col.f32.tf32.tf32.f32 "
        "{%0,%1,%2,%3}, {%4,%5,%6,%7}, {%8,%9}, {%0,%1,%2,%3};"
        : "+f"(c[0]), "+f"(c[1]), "+f"(c[2]), "+f"(c[3])
        : "r"(a[0]), "r"(a[1]), "r"(a[2]), "r"(a[3]), "r"(b[0]), "r"(b[1]));
}

__device__ __forceinline__ uint32_t sptr(const void* p) {
    return (uint32_t)__cvta_generic_to_shared(p);
}
// 16B cp.async; srcsize=0 -> zero-fill (for C-edge rows)
__device__ __forceinline__ void cpa16(uint32_t dst, const float* src, uint32_t srcsize) {
    asm volatile("cp.async.cg.shared.global [%0], [%1], 16, %2;"
                 :: "r"(dst), "l"(src), "r"(srcsize) : "memory");
}
#define CP_COMMIT() asm volatile("cp.async.commit_group;" ::: "memory")
#define CP_WAIT1()  asm volatile("cp.async.wait_group 1;" ::: "memory")

// ---------------------------------------------------------------------------
// GEMM1: scores[b][c][s] = sum_d W[c][d] * x[b][s][d]   (tf32x3, cp.async x3)
// ---------------------------------------------------------------------------
__global__ __launch_bounds__(256, 2)
void k_scores(const float* __restrict__ x, const float* __restrict__ W,
              float* __restrict__ att)
{
    extern __shared__ float sm[];
    const int tid = threadIdx.x, lane = tid & 31, warp = tid >> 5;
    const int wm = warp & 1, wn = warp >> 1;      // 2 x 4 warp grid
    const int g = lane >> 2, q = lane & 3;
    const int b = blockIdx.z, cBase = blockIdx.y * 128, sBase = blockIdx.x * 128;
    const float* xb = x + (size_t)b * S * D;

    const int lrow = tid >> 1, lcol = (tid & 1) * 16;
    const int arow = cBase + lrow;
    const uint32_t aSz = (arow < C) ? 16u : 0u;
    const float* aSrc = W + (size_t)(arow < C ? arow : 0) * D + lcol;
    const float* bSrc = xb + (size_t)(sBase + lrow) * D + lcol;
    const uint32_t sOff = (uint32_t)(lrow * 36 + lcol) * 4;
    const uint32_t smb = sptr(sm);

    // prologue: stages 0..1
#pragma unroll
    for (int st = 0; st < NSTG - 1; ++st) {
        uint32_t dA = smb + (uint32_t)st * STG1 * 4 + sOff;
        uint32_t dB = dA + TA * 4;
        const int kk = st * 32;
#pragma unroll
        for (int j = 0; j < 4; j++) {
            cpa16(dA + j * 16, aSrc + kk + j * 4, aSz);
            cpa16(dB + j * 16, bSrc + kk + j * 4, 16u);
        }
        CP_COMMIT();
    }

    float acc[4][4][4];
#pragma unroll
    for (int i = 0; i < 4; i++)
#pragma unroll
        for (int j = 0; j < 4; j++)
#pragma unroll
            for (int k = 0; k < 4; k++) acc[i][j][k] = 0.0f;

#pragma unroll 1
    for (int it = 0; it < 8; ++it) {
        CP_WAIT1();
        __syncthreads();
        {   // issue stage it+2 (empty commit past the end keeps group count fixed)
            const int st = it + NSTG - 1;
            if (st < 8) {
                uint32_t dA = smb + (uint32_t)(st % 3) * STG1 * 4 + sOff;
                uint32_t dB = dA + TA * 4;
                const int kk = st * 32;
#pragma unroll
                for (int j = 0; j < 4; j++) {
                    cpa16(dA + j * 16, aSrc + kk + j * 4, aSz);
                    cpa16(dB + j * 16, bSrc + kk + j * 4, 16u);
                }
            }
            CP_COMMIT();
        }
        const float* Ar = sm + (it % 3) * STG1;
        const float* Br = Ar + TA;

#pragma unroll
        for (int ks = 0; ks < 4; ks++) {
            const int kk = ks * 8;
            uint32_t ah[4][4], al[4][4];
#pragma unroll
            for (int mi = 0; mi < 4; mi++) {
                int i0 = (wm * 64 + mi * 16 + g) * 36 + kk + q;
                split1(Ar[i0],       ah[mi][0], al[mi][0]);
                split1(Ar[i0 + 288], ah[mi][1], al[mi][1]);
                split1(Ar[i0 + 4],   ah[mi][2], al[mi][2]);
                split1(Ar[i0 + 292], ah[mi][3], al[mi][3]);
            }
            uint32_t bh[4][2], bl[4][2];
#pragma unroll
            for (int ni = 0; ni < 4; ni++) {
                int i0 = (wn * 32 + ni * 8 + g) * 36 + kk + q;
                split1(Br[i0],     bh[ni][0], bl[ni][0]);
                split1(Br[i0 + 4], bh[ni][1], bl[ni][1]);
            }
#pragma unroll
            for (int mi = 0; mi < 4; mi++)
#pragma unroll
                for (int ni = 0; ni < 4; ni++) {
                    mma8(acc[mi][ni], ah[mi], bh[ni]);
                    mma8(acc[mi][ni], ah[mi], bl[ni]);
                    mma8(acc[mi][ni], al[mi], bh[ni]);
                }
        }
    }

    float* out = att + (size_t)b * C * S;
#pragma unroll
    for (int mi = 0; mi < 4; mi++) {
        int r = cBase + wm * 64 + mi * 16 + g;
#pragma unroll
        for (int ni = 0; ni < 4; ni++) {
            int cc = sBase + wn * 32 + ni * 8 + 2 * q;
            if (r < C)
                *(float2*)&out[(size_t)r * S + cc] = make_float2(acc[mi][ni][0], acc[mi][ni][1]);
            if (r + 8 < C)
                *(float2*)&out[(size_t)(r + 8) * S + cc] = make_float2(acc[mi][ni][2], acc[mi][ni][3]);
        }
    }
}

// ---------------------------------------------------------------------------
// Softmax over S, in place (proven; at its BW floor)
// ---------------------------------------------------------------------------
__global__ __launch_bounds__(256)
void k_softmax(float* __restrict__ att)
{
    float* p = att + (size_t)blockIdx.x * S;
    const int tid = threadIdx.x;
    float4 v[4];
    float mx = -3.4e38f;
#pragma unroll
    for (int l = 0; l < 4; l++) {
        v[l] = *(const float4*)&p[(size_t)(tid + l * 256) * 4];
        mx = fmaxf(mx, fmaxf(fmaxf(v[l].x, v[l].y), fmaxf(v[l].z, v[l].w)));
    }
    __shared__ float red[8];
#pragma unroll
    for (int o = 16; o; o >>= 1) mx = fmaxf(mx, __shfl_xor_sync(0xffffffffu, mx, o));
    if ((tid & 31) == 0) red[tid >> 5] = mx;
    __syncthreads();
    float m = red[0];
#pragma unroll
    for (int w = 1; w < 8; w++) m = fmaxf(m, red[w]);
    __syncthreads();
    float sum = 0.f;
#pragma unroll
    for (int l = 0; l < 4; l++) {
        v[l].x = __expf(v[l].x - m); v[l].y = __expf(v[l].y - m);
        v[l].z = __expf(v[l].z - m); v[l].w = __expf(v[l].w - m);
        sum += (v[l].x + v[l].y) + (v[l].z + v[l].w);
    }
#pragma unroll
    for (int o = 16; o; o >>= 1) sum += __shfl_xor_sync(0xffffffffu, sum, o);
    if ((tid & 31) == 0) red[tid >> 5] = sum;
    __syncthreads();
    float tot = 0.f;
#pragma unroll
    for (int w = 0; w < 8; w++) tot += red[w];
    const float inv = 1.0f / tot;
#pragma unroll
    for (int l = 0; l < 4; l++) {
        v[l].x *= inv; v[l].y *= inv; v[l].z *= inv; v[l].w *= inv;
        *(float4*)&p[(size_t)(tid + l * 256) * 4] = v[l];
    }
}

// ---------------------------------------------------------------------------
// GEMM2: logits[b][c][d] = sum_s att[b][c][s] * x[b][s][d]  (tf32x3, cp.async x3)
// ---------------------------------------------------------------------------
__global__ __launch_bounds__(256, 2)
void k_av(const float* __restrict__ x, const float* __restrict__ att,
          float* __restrict__ logits)
{
    extern __shared__ float sm[];
    const int tid = threadIdx.x, lane = tid & 31, warp = tid >> 5;
    const int wm = warp & 1, wn = warp >> 1;
    const int g = lane >> 2, q = lane & 3;
    const int b = blockIdx.z, cBase = blockIdx.y * 128, dBase = blockIdx.x * 128;

    const float* xb = x + (size_t)b * S * D;
    const float* ab = att + (size_t)b * C * S;

    const int lrow = tid >> 1, lcol = (tid & 1) * 16;
    const int arow = cBase + lrow;
    const uint32_t aSz = (arow < C) ? 16u : 0u;
    const float* aSrc = ab + (size_t)(arow < C ? arow : 0) * S + lcol;
    const uint32_t aOff = (uint32_t)(lrow * 36 + lcol) * 4;

    const int brow = tid >> 3, bcol = (tid & 7) * 16;   // 32 rows x 128 cols
    const float* bSrc = xb + (size_t)brow * D + dBase + bcol;
    const uint32_t bOff = (uint32_t)TA * 4 + (uint32_t)(brow * 132 + bcol) * 4;
    const uint32_t smb = sptr(sm);

#pragma unroll
    for (int st = 0; st < NSTG - 1; ++st) {
        uint32_t base = smb + (uint32_t)st * STG2 * 4;
        const int kk = st * 32;
#pragma unroll
        for (int j = 0; j < 4; j++) {
            cpa16(base + aOff + j * 16, aSrc + kk + j * 4, aSz);
            cpa16(base + bOff + j * 16, bSrc + (size_t)kk * D + j * 4, 16u);
        }
        CP_COMMIT();
    }

    float acc[4][4][4];
#pragma unroll
    for (int i = 0; i < 4; i++)
#pragma unroll
        for (int j = 0; j < 4; j++)
#pragma unroll
            for (int k = 0; k < 4; k++) acc[i][j][k] = 0.0f;

#pragma unroll 1
    for (int it = 0; it < 128; ++it) {
        CP_WAIT1();
        __syncthreads();
        {
            const int st = it + NSTG - 1;
            if (st < 128) {
                uint32_t base = smb + (uint32_t)(st % 3) * STG2 * 4;
                const int kk = st * 32;
#pragma unroll
                for (int j = 0; j < 4; j++) {
                    cpa16(base + aOff + j * 16, aSrc + kk + j * 4, aSz);
                    cpa16(base + bOff + j * 16, bSrc + (size_t)kk * D + j * 4, 16u);
                }
            }
            CP_COMMIT();
        }
        const float* Ar = sm + (it % 3) * STG2;
        const float* Br = Ar + TA;

#pragma unroll
        for (int ks = 0; ks < 4; ks++) {
            const int kk = ks * 8;
            uint32_t ah[4][4], al[4][4];
#pragma unroll
            for (int mi = 0; mi < 4; mi++) {
                int i0 = (wm * 64 + mi * 16 + g) * 36 + kk + q;
                split1(Ar[i0],       ah[mi][0], al[mi][0]);
                split1(Ar[i0 + 288], ah[mi][1], al[mi][1]);
                split1(Ar[i0 + 4],   ah[mi][2], al[mi][2]);
                split1(Ar[i0 + 292], ah[mi][3], al[mi][3]);
            }
            uint32_t bh[4][2], bl[4][2];
#pragma unroll
            for (int ni = 0; ni < 4; ni++) {
                int i0 = (kk + q) * 132 + wn * 32 + ni * 8 + g;
                split1(Br[i0],       bh[ni][0], bl[ni][0]);
                split1(Br[i0 + 528], bh[ni][1], bl[ni][1]);   // +4 k rows
            }
#pragma unroll
            for (int mi = 0; mi < 4; mi++)
#pragma unroll
                for (int ni = 0; ni < 4; ni++) {
                    mma8(acc[mi][ni], ah[mi], bh[ni]);
                    mma8(acc[mi][ni], ah[mi], bl[ni]);
                    mma8(acc[mi][ni], al[mi], bh[ni]);
                }
        }
    }

    float* out = logits + (size_t)b * C * D;
#pragma unroll
    for (int mi = 0; mi < 4; mi++) {
        int r = cBase + wm * 64 + mi * 16 + g;
#pragma unroll
        for (int ni = 0; ni < 4; ni++) {
            int cc = dBase + wn * 32 + ni * 8 + 2 * q;
            if (r < C)
                *(float2*)&out[(size_t)r * D + cc] = make_float2(acc[mi][ni][0], acc[mi][ni][1]);
            if (r + 8 < C)
                *(float2*)&out[(size_t)(r + 8) * D + cc] = make_float2(acc[mi][ni][2], acc[mi][ni][3]);
        }
    }
}

// ---------------------------------------------------------------------------
extern "C" void kernel_launch(void* const* d_in, const int* in_sizes, int n_in,
                              void* d_out, int out_size)
{
    const float* x = (const float*)d_in[0];  // [B, S, D]
    const float* W = (const float*)d_in[1];  // [C, D]
    float* logits = (float*)d_out;                        // [B, C, D]
    float* att    = (float*)d_out + (size_t)Bsz * C * D;  // [B, C, S]

    cudaFuncSetAttribute(k_scores, cudaFuncAttributeMaxDynamicSharedMemorySize, SM1);
    cudaFuncSetAttribute(k_av, cudaFuncAttributeMaxDynamicSharedMemorySize, SM2);

    k_scores<<<dim3(S / 128, CT, Bsz), 256, SM1>>>(x, W, att);
    k_softmax<<<Bsz * C, 256>>>(att);
    k_av<<<dim3(D / 128, CT, Bsz), 256, SM2>>>(x, att, logits);
}

// round 17
// speedup vs baseline: 1.3520x; 1.1711x over previous
#include <cuda_runtime.h>
#include <cstddef>
#include <cstdint>

constexpr int Bsz = 4, S = 4096, D = 256, C = 8921;
constexpr int CT = (C + 127) / 128;  // 70

// Raw fp32 smem tiles. A-type: [128 rows][32 k + 4 pad]. GEMM2 B: [32 k][128 n + 4 pad].
constexpr int TA   = 128 * 36;          // 4608 floats
constexpr int TB2  = 32 * 132;          // 4224 floats
constexpr int STG1 = 2 * TA;            // A + B (GEMM1), floats
constexpr int STG2 = TA + TB2;          // A + B (GEMM2), floats
constexpr int NSTG = 3;
constexpr int SM1  = NSTG * STG1 * 4;   // 110592 B  -> 2 CTAs/SM
constexpr int SM2  = NSTG * STG2 * 4;   // 105984 B  -> 2 CTAs/SM

__device__ __forceinline__ uint32_t t32(float v) {
    uint32_t u;
    asm("cvt.rna.tf32.f32 %0, %1;" : "=r"(u) : "f"(v));
    return u;
}
// tf32 split: hi rounded, lo = residual as raw fp32 bits (proven R13)
__device__ __forceinline__ void split1(float v, uint32_t& h, uint32_t& l) {
    h = t32(v);
    l = __float_as_uint(v - __uint_as_float(h));
}
// bf16 pair split: (v0,v1) -> bf16x2 hi + bf16x2 lo  (v0 in low half)
__device__ __forceinline__ void splitp(float v0, float v1, uint32_t& h, uint32_t& l) {
    asm("cvt.rn.bf16x2.f32 %0, %1, %2;" : "=r"(h) : "f"(v1), "f"(v0));
    float h0 = __uint_as_float(h << 16);
    float h1 = __uint_as_float(h & 0xffff0000u);
    float r0 = v0 - h0, r1 = v1 - h1;
    asm("cvt.rn.bf16x2.f32 %0, %1, %2;" : "=r"(l) : "f"(r1), "f"(r0));
}

__device__ __forceinline__ void mma8(float* c, const uint32_t* a, const uint32_t* b) {
    asm volatile(
        "mma.sync.aligned.m16n8k8.row.col.f32.tf32.tf32.f32 "
        "{%0,%1,%2,%3}, {%4,%5,%6,%7}, {%8,%9}, {%0,%1,%2,%3};"
        : "+f"(c[0]), "+f"(c[1]), "+f"(c[2]), "+f"(c[3])
        : "r"(a[0]), "r"(a[1]), "r"(a[2]), "r"(a[3]), "r"(b[0]), "r"(b[1]));
}
__device__ __forceinline__ void mma16(float* c, const uint32_t* a, const uint32_t* b) {
    asm volatile(
        "mma.sync.aligned.m16n8k16.row.col.f32.bf16.bf16.f32 "
        "{%0,%1,%2,%3}, {%4,%5,%6,%7}, {%8,%9}, {%0,%1,%2,%3};"
        : "+f"(c[0]), "+f"(c[1]), "+f"(c[2]), "+f"(c[3])
        : "r"(a[0]), "r"(a[1]), "r"(a[2]), "r"(a[3]), "r"(b[0]), "r"(b[1]));
}

__device__ __forceinline__ uint32_t sptr(const void* p) {
    return (uint32_t)__cvta_generic_to_shared(p);
}
// 16B cp.async; srcsize=0 -> zero-fill (for C-edge rows)
__device__ __forceinline__ void cpa16(uint32_t dst, const float* src, uint32_t srcsize) {
    asm volatile("cp.async.cg.shared.global [%0], [%1], 16, %2;"
                 :: "r"(dst), "l"(src), "r"(srcsize) : "memory");
}
#define CP_COMMIT() asm volatile("cp.async.commit_group;" ::: "memory")
#define CP_WAIT1()  asm volatile("cp.async.wait_group 1;" ::: "memory")

// ---------------------------------------------------------------------------
// GEMM1: scores[b][c][s] = sum_d W[c][d] * x[b][s][d]   (tf32x3, cp.async x3)
// (unchanged from R15 — protects attention precision)
// ---------------------------------------------------------------------------
__global__ __launch_bounds__(256, 2)
void k_scores(const float* __restrict__ x, const float* __restrict__ W,
              float* __restrict__ att)
{
    extern __shared__ float sm[];
    const int tid = threadIdx.x, lane = tid & 31, warp = tid >> 5;
    const int wm = warp & 1, wn = warp >> 1;      // 2 x 4 warp grid
    const int g = lane >> 2, q = lane & 3;
    const int b = blockIdx.z, cBase = blockIdx.y * 128, sBase = blockIdx.x * 128;
    const float* xb = x + (size_t)b * S * D;

    const int lrow = tid >> 1, lcol = (tid & 1) * 16;
    const int arow = cBase + lrow;
    const uint32_t aSz = (arow < C) ? 16u : 0u;
    const float* aSrc = W + (size_t)(arow < C ? arow : 0) * D + lcol;
    const float* bSrc = xb + (size_t)(sBase + lrow) * D + lcol;
    const uint32_t sOff = (uint32_t)(lrow * 36 + lcol) * 4;
    const uint32_t smb = sptr(sm);

#pragma unroll
    for (int st = 0; st < NSTG - 1; ++st) {
        uint32_t dA = smb + (uint32_t)st * STG1 * 4 + sOff;
        uint32_t dB = dA + TA * 4;
        const int kk = st * 32;
#pragma unroll
        for (int j = 0; j < 4; j++) {
            cpa16(dA + j * 16, aSrc + kk + j * 4, aSz);
            cpa16(dB + j * 16, bSrc + kk + j * 4, 16u);
        }
        CP_COMMIT();
    }

    float acc[4][4][4];
#pragma unroll
    for (int i = 0; i < 4; i++)
#pragma unroll
        for (int j = 0; j < 4; j++)
#pragma unroll
            for (int k = 0; k < 4; k++) acc[i][j][k] = 0.0f;

#pragma unroll 1
    for (int it = 0; it < 8; ++it) {
        CP_WAIT1();
        __syncthreads();
        {
            const int st = it + NSTG - 1;
            if (st < 8) {
                uint32_t dA = smb + (uint32_t)(st % 3) * STG1 * 4 + sOff;
                uint32_t dB = dA + TA * 4;
                const int kk = st * 32;
#pragma unroll
                for (int j = 0; j < 4; j++) {
                    cpa16(dA + j * 16, aSrc + kk + j * 4, aSz);
                    cpa16(dB + j * 16, bSrc + kk + j * 4, 16u);
                }
            }
            CP_COMMIT();
        }
        const float* Ar = sm + (it % 3) * STG1;
        const float* Br = Ar + TA;

#pragma unroll
        for (int ks = 0; ks < 4; ks++) {
            const int kk = ks * 8;
            uint32_t ah[4][4], al[4][4];
#pragma unroll
            for (int mi = 0; mi < 4; mi++) {
                int i0 = (wm * 64 + mi * 16 + g) * 36 + kk + q;
                split1(Ar[i0],       ah[mi][0], al[mi][0]);
                split1(Ar[i0 + 288], ah[mi][1], al[mi][1]);
                split1(Ar[i0 + 4],   ah[mi][2], al[mi][2]);
                split1(Ar[i0 + 292], ah[mi][3], al[mi][3]);
            }
            uint32_t bh[4][2], bl[4][2];
#pragma unroll
            for (int ni = 0; ni < 4; ni++) {
                int i0 = (wn * 32 + ni * 8 + g) * 36 + kk + q;
                split1(Br[i0],     bh[ni][0], bl[ni][0]);
                split1(Br[i0 + 4], bh[ni][1], bl[ni][1]);
            }
#pragma unroll
            for (int mi = 0; mi < 4; mi++)
#pragma unroll
                for (int ni = 0; ni < 4; ni++) {
                    mma8(acc[mi][ni], ah[mi], bh[ni]);
                    mma8(acc[mi][ni], ah[mi], bl[ni]);
                    mma8(acc[mi][ni], al[mi], bh[ni]);
                }
        }
    }

    float* out = att + (size_t)b * C * S;
#pragma unroll
    for (int mi = 0; mi < 4; mi++) {
        int r = cBase + wm * 64 + mi * 16 + g;
#pragma unroll
        for (int ni = 0; ni < 4; ni++) {
            int cc = sBase + wn * 32 + ni * 8 + 2 * q;
            if (r < C)
                *(float2*)&out[(size_t)r * S + cc] = make_float2(acc[mi][ni][0], acc[mi][ni][1]);
            if (r + 8 < C)
                *(float2*)&out[(size_t)(r + 8) * S + cc] = make_float2(acc[mi][ni][2], acc[mi][ni][3]);
        }
    }
}

// ---------------------------------------------------------------------------
// Softmax over S, in place (proven; at its BW floor)
// ---------------------------------------------------------------------------
__global__ __launch_bounds__(256)
void k_softmax(float* __restrict__ att)
{
    float* p = att + (size_t)blockIdx.x * S;
    const int tid = threadIdx.x;
    float4 v[4];
    float mx = -3.4e38f;
#pragma unroll
    for (int l = 0; l < 4; l++) {
        v[l] = *(const float4*)&p[(size_t)(tid + l * 256) * 4];
        mx = fmaxf(mx, fmaxf(fmaxf(v[l].x, v[l].y), fmaxf(v[l].z, v[l].w)));
    }
    __shared__ float red[8];
#pragma unroll
    for (int o = 16; o; o >>= 1) mx = fmaxf(mx, __shfl_xor_sync(0xffffffffu, mx, o));
    if ((tid & 31) == 0) red[tid >> 5] = mx;
    __syncthreads();
    float m = red[0];
#pragma unroll
    for (int w = 1; w < 8; w++) m = fmaxf(m, red[w]);
    __syncthreads();
    float sum = 0.f;
#pragma unroll
    for (int l = 0; l < 4; l++) {
        v[l].x = __expf(v[l].x - m); v[l].y = __expf(v[l].y - m);
        v[l].z = __expf(v[l].z - m); v[l].w = __expf(v[l].w - m);
        sum += (v[l].x + v[l].y) + (v[l].z + v[l].w);
    }
#pragma unroll
    for (int o = 16; o; o >>= 1) sum += __shfl_xor_sync(0xffffffffu, sum, o);
    if ((tid & 31) == 0) red[tid >> 5] = sum;
    __syncthreads();
    float tot = 0.f;
#pragma unroll
    for (int w = 0; w < 8; w++) tot += red[w];
    const float inv = 1.0f / tot;
#pragma unroll
    for (int l = 0; l < 4; l++) {
        v[l].x *= inv; v[l].y *= inv; v[l].z *= inv; v[l].w *= inv;
        *(float4*)&p[(size_t)(tid + l * 256) * 4] = v[l];
    }
}

// ---------------------------------------------------------------------------
// GEMM2: logits[b][c][d] = sum_s att[b][c][s] * x[b][s][d]
// bf16x3 via m16n8k16 (half the MMA instructions of tf32x3), cp.async x3
// ---------------------------------------------------------------------------
__global__ __launch_bounds__(256, 2)
void k_av(const float* __restrict__ x, const float* __restrict__ att,
          float* __restrict__ logits)
{
    extern __shared__ float sm[];
    const int tid = threadIdx.x, lane = tid & 31, warp = tid >> 5;
    const int wm = warp & 1, wn = warp >> 1;
    const int g = lane >> 2, q = lane & 3;
    const int b = blockIdx.z, cBase = blockIdx.y * 128, dBase = blockIdx.x * 128;

    const float* xb = x + (size_t)b * S * D;
    const float* ab = att + (size_t)b * C * S;

    const int lrow = tid >> 1, lcol = (tid & 1) * 16;
    const int arow = cBase + lrow;
    const uint32_t aSz = (arow < C) ? 16u : 0u;
    const float* aSrc = ab + (size_t)(arow < C ? arow : 0) * S + lcol;
    const uint32_t aOff = (uint32_t)(lrow * 36 + lcol) * 4;

    const int brow = tid >> 3, bcol = (tid & 7) * 16;   // 32 rows x 128 cols
    const float* bSrc = xb + (size_t)brow * D + dBase + bcol;
    const uint32_t bOff = (uint32_t)TA * 4 + (uint32_t)(brow * 132 + bcol) * 4;
    const uint32_t smb = sptr(sm);

#pragma unroll
    for (int st = 0; st < NSTG - 1; ++st) {
        uint32_t base = smb + (uint32_t)st * STG2 * 4;
        const int kk = st * 32;
#pragma unroll
        for (int j = 0; j < 4; j++) {
            cpa16(base + aOff + j * 16, aSrc + kk + j * 4, aSz);
            cpa16(base + bOff + j * 16, bSrc + (size_t)kk * D + j * 4, 16u);
        }
        CP_COMMIT();
    }

    float acc[4][4][4];
#pragma unroll
    for (int i = 0; i < 4; i++)
#pragma unroll
        for (int j = 0; j < 4; j++)
#pragma unroll
            for (int k = 0; k < 4; k++) acc[i][j][k] = 0.0f;

#pragma unroll 1
    for (int it = 0; it < 128; ++it) {
        CP_WAIT1();
        __syncthreads();
        {
            const int st = it + NSTG - 1;
            if (st < 128) {
                uint32_t base = smb + (uint32_t)(st % 3) * STG2 * 4;
                const int kk = st * 32;
#pragma unroll
                for (int j = 0; j < 4; j++) {
                    cpa16(base + aOff + j * 16, aSrc + kk + j * 4, aSz);
                    cpa16(base + bOff + j * 16, bSrc + (size_t)kk * D + j * 4, 16u);
                }
            }
            CP_COMMIT();
        }
        const float* Ar = sm + (it % 3) * STG2;
        const float* Br = Ar + TA;

        // two K=16 groups per BK=32 iteration
#pragma unroll
        for (int grp = 0; grp < 2; grp++) {
            const int kk = grp * 16;
            // A fragments: att tile [c][k], row-major; pairs at k=2q,2q+1 and +8
            uint32_t ah[4][4], al[4][4];
#pragma unroll
            for (int mi = 0; mi < 4; mi++) {
                int r0 = (wm * 64 + mi * 16 + g) * 36 + kk + 2 * q;
                float2 v00 = *(const float2*)&Ar[r0];            // a0: row g
                float2 v10 = *(const float2*)&Ar[r0 + 288];      // a1: row g+8
                float2 v01 = *(const float2*)&Ar[r0 + 8];        // a2: row g, k+8
                float2 v11 = *(const float2*)&Ar[r0 + 296];      // a3: row g+8, k+8
                splitp(v00.x, v00.y, ah[mi][0], al[mi][0]);
                splitp(v10.x, v10.y, ah[mi][1], al[mi][1]);
                splitp(v01.x, v01.y, ah[mi][2], al[mi][2]);
                splitp(v11.x, v11.y, ah[mi][3], al[mi][3]);
            }
            // B fragments: x tile [k][n]; b0 = rows 2q,2q+1 @ col; b1 = rows 2q+8,2q+9
            uint32_t bh[4][2], bl[4][2];
#pragma unroll
            for (int ni = 0; ni < 4; ni++) {
                int col = wn * 32 + ni * 8 + g;
                int r0 = (kk + 2 * q) * 132 + col;
                splitp(Br[r0],            Br[r0 + 132],  bh[ni][0], bl[ni][0]);
                splitp(Br[r0 + 8 * 132],  Br[r0 + 9 * 132], bh[ni][1], bl[ni][1]);
            }
#pragma unroll
            for (int mi = 0; mi < 4; mi++)
#pragma unroll
                for (int ni = 0; ni < 4; ni++) {
                    mma16(acc[mi][ni], ah[mi], bh[ni]);
                    mma16(acc[mi][ni], ah[mi], bl[ni]);
                    mma16(acc[mi][ni], al[mi], bh[ni]);
                }
        }
    }

    float* out = logits + (size_t)b * C * D;
#pragma unroll
    for (int mi = 0; mi < 4; mi++) {
        int r = cBase + wm * 64 + mi * 16 + g;
#pragma unroll
        for (int ni = 0; ni < 4; ni++) {
            int cc = dBase + wn * 32 + ni * 8 + 2 * q;
            if (r < C)
                *(float2*)&out[(size_t)r * D + cc] = make_float2(acc[mi][ni][0], acc[mi][ni][1]);
            if (r + 8 < C)
                *(float2*)&out[(size_t)(r + 8) * D + cc] = make_float2(acc[mi][ni][2], acc[mi][ni][3]);
        }
    }
}

// ---------------------------------------------------------------------------
extern "C" void kernel_launch(void* const* d_in, const int* in_sizes, int n_in,
                              void* d_out, int out_size)
{
    const float* x = (const float*)d_in[0];  // [B, S, D]
    const float* W = (const float*)d_in[1];  // [C, D]
    float* logits = (float*)d_out;                        // [B, C, D]
    float* att    = (float*)d_out + (size_t)Bsz * C * D;  // [B, C, S]

    cudaFuncSetAttribute(k_scores, cudaFuncAttributeMaxDynamicSharedMemorySize, SM1);
    cudaFuncSetAttribute(k_av, cudaFuncAttributeMaxDynamicSharedMemorySize, SM2);

    k_scores<<<dim3(S / 128, CT, Bsz), 256, SM1>>>(x, W, att);
    k_softmax<<<Bsz * C, 256>>>(att);
    k_av<<<dim3(D / 128, CT, Bsz), 256, SM2>>>(x, att, logits);
}